// round 1
// baseline (speedup 1.0000x reference)
#include <cuda_runtime.h>
#include <cuda_bf16.h>

#define NN 50000
#define EE 500000
#define DD 256
#define HH 4
#define MAXDEG 96

// ------------------- device scratch (no allocations allowed) -------------------
__device__ float g_Wcat[256 * 384];     // [D, 384]: cols 0-127 = Wv, 128-255 = Wkq*aw1, 256-383 = Wkq*aw2
__device__ float g_big[NN * 384];       // [N, 384]: v | A_src | A_tgt
__device__ float g_Apos[129 * 128];     // [pos, h*32+k]
__device__ float g_Bdr[64 * 4];         // [deprel, h]
__device__ float g_Bda[8 * 4];          // [deparc, h]
__device__ float g_exp[EE * 128];       // exp scores per edge [e, h*32+k]
__device__ float g_agg[NN * 128];       // aggregated v*score per node
__device__ int   g_cnt[NN];
__device__ int   g_slot[NN * MAXDEG];

// ------------------- small prep kernels -------------------
__global__ void zero_cnt_kernel() {
    int i = blockIdx.x * blockDim.x + threadIdx.x;
    if (i < NN) g_cnt[i] = 0;
}

__global__ void scatter_kernel(const int* __restrict__ edge_index) {
    int e = blockIdx.x * blockDim.x + threadIdx.x;
    if (e >= EE) return;
    int t = edge_index[EE + e];               // tgt
    int r = atomicAdd(&g_cnt[t], 1);
    if (r < MAXDEG) g_slot[t * MAXDEG + r] = e;
}

// Build Wcat[d][c]: fold att_w halves into Wkq
__global__ void prep_weights_kernel(const float* __restrict__ Wkq,
                                    const float* __restrict__ Wv,
                                    const float* __restrict__ att_w) {
    int t = blockIdx.x * blockDim.x + threadIdx.x;
    if (t >= 256 * 384) return;
    int d = t / 384, c = t % 384;
    float o;
    if (c < 128) {
        o = Wv[d * 128 + c];
    } else {
        int sec = (c >= 256) ? 1 : 0;
        int m = c - 128 - sec * 128;
        int h = m >> 5, k = m & 31;
        int joff = sec ? 32 : 0;
        float s = 0.f;
        #pragma unroll
        for (int j = 0; j < 32; j++)
            s += Wkq[d * 128 + h * 32 + j] * att_w[h * 3072 + (joff + j) * 32 + k];
        o = s;
    }
    g_Wcat[t] = o;
}

// A_pos table, Bdr, Bda tables
__global__ void prep_tables_kernel(const float* __restrict__ E_pos,
                                   const float* __restrict__ E_deprel,
                                   const float* __restrict__ E_deparc,
                                   const float* __restrict__ att_w,
                                   const float* __restrict__ edge_w) {
    int t = blockIdx.x * blockDim.x + threadIdx.x;
    if (t < 129 * 128) {
        int p = t / 128, m = t % 128;
        int h = m >> 5, k = m & 31;
        float s = 0.f;
        #pragma unroll
        for (int j = 0; j < 32; j++)
            s += E_pos[p * 32 + j] * att_w[h * 3072 + (64 + j) * 32 + k];
        g_Apos[t] = s;
    } else if (t < 129 * 128 + 256) {
        int i = t - 129 * 128;
        int r = i / 4, h = i % 4;
        float s = 0.f;
        #pragma unroll
        for (int j = 0; j < 32; j++)
            s += E_deprel[r * 32 + j] * edge_w[h * 96 + j];
        g_Bdr[i] = s;
    } else if (t < 129 * 128 + 256 + 32) {
        int i = t - 129 * 128 - 256;
        int a = i / 4, h = i % 4;
        float s = 0.f;
        #pragma unroll
        for (int j = 0; j < 32; j++)
            s += E_deparc[a * 32 + j] * edge_w[h * 96 + 32 + j];
        g_Bda[i] = s;
    }
}

// ------------------- SGEMM (BM=128, BN=64, BK=16, 256 thr, 8x4 micro) -------------------
__device__ __forceinline__ void sgemm_body(int M, int K,
                                           const float* __restrict__ A, int lda,
                                           const float* __restrict__ B, int ldb,
                                           float* __restrict__ C, int ldc,
                                           const float* __restrict__ bias,
                                           float* As /*[16][128]*/, float* Bs /*[16][64]*/) {
    int m0 = blockIdx.y * 128;
    int n0 = blockIdx.x * 64;
    int tid = threadIdx.x;
    int tx = tid & 15, ty = tid >> 4;

    float acc[8][4];
    #pragma unroll
    for (int i = 0; i < 8; i++)
        #pragma unroll
        for (int j = 0; j < 4; j++) acc[i][j] = 0.f;

    for (int k0 = 0; k0 < K; k0 += 16) {
        // load A tile (128x16), transposed into As[k][m]
        #pragma unroll
        for (int l = 0; l < 2; l++) {
            int q = tid + l * 256;
            int row = q >> 2;
            int kc = (q & 3) * 4;
            float4 av = make_float4(0.f, 0.f, 0.f, 0.f);
            if (m0 + row < M)
                av = *(const float4*)(A + (size_t)(m0 + row) * lda + k0 + kc);
            As[(kc + 0) * 128 + row] = av.x;
            As[(kc + 1) * 128 + row] = av.y;
            As[(kc + 2) * 128 + row] = av.z;
            As[(kc + 3) * 128 + row] = av.w;
        }
        // load B tile (16x64)
        {
            int row = tid >> 4;
            int c4 = (tid & 15) * 4;
            float4 bv = *(const float4*)(B + (size_t)(k0 + row) * ldb + n0 + c4);
            *(float4*)(Bs + row * 64 + c4) = bv;
        }
        __syncthreads();
        #pragma unroll
        for (int kk = 0; kk < 16; kk++) {
            float a[8], b[4];
            *(float4*)(a)     = *(const float4*)(As + kk * 128 + ty * 8);
            *(float4*)(a + 4) = *(const float4*)(As + kk * 128 + ty * 8 + 4);
            *(float4*)(b)     = *(const float4*)(Bs + kk * 64 + tx * 4);
            #pragma unroll
            for (int i = 0; i < 8; i++)
                #pragma unroll
                for (int j = 0; j < 4; j++)
                    acc[i][j] += a[i] * b[j];
        }
        __syncthreads();
    }

    float bv[4] = {0.f, 0.f, 0.f, 0.f};
    if (bias) {
        float4 b4 = *(const float4*)(bias + n0 + tx * 4);
        bv[0] = b4.x; bv[1] = b4.y; bv[2] = b4.z; bv[3] = b4.w;
    }
    #pragma unroll
    for (int i = 0; i < 8; i++) {
        int row = m0 + ty * 8 + i;
        if (row < M) {
            float4 o = make_float4(acc[i][0] + bv[0], acc[i][1] + bv[1],
                                   acc[i][2] + bv[2], acc[i][3] + bv[3]);
            *(float4*)(C + (size_t)row * ldc + n0 + tx * 4) = o;
        }
    }
}

__global__ void gemm1_kernel(const float* __restrict__ inp) {
    __shared__ float As[16 * 128];
    __shared__ float Bs[16 * 64];
    sgemm_body(NN, 256, inp, 256, g_Wcat, 384, g_big, 384, nullptr, As, Bs);
}

__global__ void gemm2_kernel(const float* __restrict__ Wf,
                             const float* __restrict__ bias,
                             float* __restrict__ out) {
    __shared__ float As[16 * 128];
    __shared__ float Bs[16 * 64];
    sgemm_body(NN, 128, g_agg, 128, Wf, 256, out, 256, bias, As, Bs);
}

// ------------------- edge/attention kernel: one warp per target node -------------------
__device__ __forceinline__ float warpsum(float v) {
    #pragma unroll
    for (int o = 16; o > 0; o >>= 1) v += __shfl_xor_sync(0xffffffffu, v, o);
    return v;
}

__global__ void edge_kernel(const int* __restrict__ edge_index,
                            const int* __restrict__ relpos,
                            const int* __restrict__ deprel,
                            const int* __restrict__ deparc,
                            const float* __restrict__ edge_w,
                            float* __restrict__ attn) {
    int warp = (blockIdx.x * blockDim.x + threadIdx.x) >> 5;
    int lane = threadIdx.x & 31;
    if (warp >= NN) return;
    int n = warp;
    const int* src = edge_index;

    float at[4], ew[4], den[4], acc[4];
    #pragma unroll
    for (int h = 0; h < 4; h++) {
        at[h]  = g_big[n * 384 + 256 + h * 32 + lane];
        ew[h]  = edge_w[h * 96 + 64 + lane];
        den[h] = 0.f;
        acc[h] = 0.f;
    }

    int d = g_cnt[n];
    if (d > MAXDEG) d = MAXDEG;
    const int* sl = g_slot + n * MAXDEG;

    // pass 1: exp scores + denominators
    for (int i = 0; i < d; i++) {
        int e = sl[i];
        int s = src[e];
        int p = relpos[e] + 64;
        const float* as = g_big + s * 384 + 128;
        const float* ap = g_Apos + p * 128;
        #pragma unroll
        for (int h = 0; h < 4; h++) {
            float x = as[h * 32 + lane] + at[h] + ap[h * 32 + lane];
            x = (x >= 0.f) ? x : 0.2f * x;          // leaky
            float ex = __expf(x);
            den[h] += ex;
            g_exp[e * 128 + h * 32 + lane] = ex;
        }
    }

    // pass 2: edge scores, attn output, weighted v accumulation
    for (int i = 0; i < d; i++) {
        int e = sl[i];
        int s = src[e];
        const float* ep = g_exp + e * 128;
        const float* vv = g_big + s * 384;
        int dr = deprel[e], da = deparc[e];
        float es0, es1, es2, es3;
        {
            float b = warpsum(ep[0 * 32 + lane] * ew[0] / (den[0] + 1e-12f));
            float x = g_Bdr[dr * 4 + 0] + g_Bda[da * 4 + 0] + b;
            es0 = (x >= 0.f) ? x : 0.2f * x;
            acc[0] += vv[0 * 32 + lane] * es0;
        }
        {
            float b = warpsum(ep[1 * 32 + lane] * ew[1] / (den[1] + 1e-12f));
            float x = g_Bdr[dr * 4 + 1] + g_Bda[da * 4 + 1] + b;
            es1 = (x >= 0.f) ? x : 0.2f * x;
            acc[1] += vv[1 * 32 + lane] * es1;
        }
        {
            float b = warpsum(ep[2 * 32 + lane] * ew[2] / (den[2] + 1e-12f));
            float x = g_Bdr[dr * 4 + 2] + g_Bda[da * 4 + 2] + b;
            es2 = (x >= 0.f) ? x : 0.2f * x;
            acc[2] += vv[2 * 32 + lane] * es2;
        }
        {
            float b = warpsum(ep[3 * 32 + lane] * ew[3] / (den[3] + 1e-12f));
            float x = g_Bdr[dr * 4 + 3] + g_Bda[da * 4 + 3] + b;
            es3 = (x >= 0.f) ? x : 0.2f * x;
            acc[3] += vv[3 * 32 + lane] * es3;
        }
        if (lane == 0)
            *(float4*)(attn + (size_t)e * 4) = make_float4(es0, es1, es2, es3);
    }

    #pragma unroll
    for (int h = 0; h < 4; h++)
        g_agg[n * 128 + h * 32 + lane] = acc[h];
}

// ------------------- launch -------------------
extern "C" void kernel_launch(void* const* d_in, const int* in_sizes, int n_in,
                              void* d_out, int out_size) {
    const float* inp       = (const float*)d_in[0];
    const int*   relpos    = (const int*)d_in[1];
    // d_in[2] word_rel_pos_edge: unused
    // d_in[3] deprel_ext_edge: unused
    const int*   edge_index = (const int*)d_in[4];
    const int*   deprel    = (const int*)d_in[5];
    const int*   deparc    = (const int*)d_in[6];
    const float* Wkq       = (const float*)d_in[7];
    const float* Wv        = (const float*)d_in[8];
    const float* att_w     = (const float*)d_in[9];
    const float* edge_w    = (const float*)d_in[10];
    const float* Wf        = (const float*)d_in[11];
    const float* final_bias = (const float*)d_in[12];
    const float* E_deprel  = (const float*)d_in[13];
    const float* E_deparc  = (const float*)d_in[14];
    const float* E_pos     = (const float*)d_in[15];

    float* out  = (float*)d_out;             // [N, 256]
    float* attn = out + (size_t)NN * DD;     // [E, 4]

    zero_cnt_kernel<<<(NN + 255) / 256, 256>>>();
    prep_weights_kernel<<<(256 * 384 + 255) / 256, 256>>>(Wkq, Wv, att_w);
    prep_tables_kernel<<<(129 * 128 + 256 + 32 + 255) / 256, 256>>>(E_pos, E_deprel, E_deparc, att_w, edge_w);
    scatter_kernel<<<(EE + 255) / 256, 256>>>(edge_index);

    {
        dim3 grid(384 / 64, (NN + 127) / 128);
        gemm1_kernel<<<grid, 256>>>(inp);
    }

    edge_kernel<<<(NN * 32 + 255) / 256, 256>>>(edge_index, relpos, deprel, deparc, edge_w, attn);

    {
        dim3 grid(256 / 64, (NN + 127) / 128);
        gemm2_kernel<<<grid, 256>>>(Wf, final_bias, out);
    }
}

// round 2
// speedup vs baseline: 2.1005x; 2.1005x over previous
#include <cuda_runtime.h>
#include <cuda_bf16.h>

#define NN 50000
#define EE 500000
#define DD 256
#define HH 4
#define MAXDEG 96

// ------------------- device scratch (no allocations allowed) -------------------
__device__ float g_WcatT[384 * 256];    // [n=384][k=256]: rows 0-127 Wv^T, 128-255 (Wkq*aw1)^T, 256-383 (Wkq*aw2)^T
__device__ float g_WfT[256 * 128];      // [n=256][k=128] = Wf^T
__device__ float g_big[NN * 384];       // [N, 384]: v | A_src | A_tgt
__device__ float g_Apos[129 * 128];     // [pos, h*32+k]
__device__ float g_Bdr[64 * 4];         // [deprel, h]
__device__ float g_Bda[8 * 4];          // [deparc, h]
__device__ float g_agg[NN * 128];       // aggregated v*score per node
__device__ int   g_cnt[NN];
__device__ int   g_slot[NN * MAXDEG];

// ------------------- small prep kernels -------------------
__global__ void zero_cnt_kernel() {
    int i = blockIdx.x * blockDim.x + threadIdx.x;
    if (i < NN) g_cnt[i] = 0;
}

__global__ void scatter_kernel(const int* __restrict__ edge_index) {
    int e = blockIdx.x * blockDim.x + threadIdx.x;
    if (e >= EE) return;
    int t = edge_index[EE + e];               // tgt
    int r = atomicAdd(&g_cnt[t], 1);
    if (r < MAXDEG) g_slot[t * MAXDEG + r] = e;
}

// Build WcatT[c][d]: fold att_w halves into Wkq (stored transposed, n-major)
__global__ void prep_weights_kernel(const float* __restrict__ Wkq,
                                    const float* __restrict__ Wv,
                                    const float* __restrict__ att_w,
                                    const float* __restrict__ Wf) {
    int t = blockIdx.x * blockDim.x + threadIdx.x;
    if (t < 256 * 384) {
        int d = t / 384, c = t % 384;
        float o;
        if (c < 128) {
            o = Wv[d * 128 + c];
        } else {
            int sec = (c >= 256) ? 1 : 0;
            int m = c - 128 - sec * 128;
            int h = m >> 5, k = m & 31;
            int joff = sec ? 32 : 0;
            float s = 0.f;
            #pragma unroll
            for (int j = 0; j < 32; j++)
                s += Wkq[d * 128 + h * 32 + j] * att_w[h * 3072 + (joff + j) * 32 + k];
            o = s;
        }
        g_WcatT[c * 256 + d] = o;
    } else if (t < 256 * 384 + 128 * 256) {
        int i = t - 256 * 384;
        int k = i / 256, n = i % 256;        // Wf is [128][256] row-major
        g_WfT[n * 128 + k] = Wf[k * 256 + n];
    }
}

// A_pos table, Bdr, Bda tables
__global__ void prep_tables_kernel(const float* __restrict__ E_pos,
                                   const float* __restrict__ E_deprel,
                                   const float* __restrict__ E_deparc,
                                   const float* __restrict__ att_w,
                                   const float* __restrict__ edge_w) {
    int t = blockIdx.x * blockDim.x + threadIdx.x;
    if (t < 129 * 128) {
        int p = t / 128, m = t % 128;
        int h = m >> 5, k = m & 31;
        float s = 0.f;
        #pragma unroll
        for (int j = 0; j < 32; j++)
            s += E_pos[p * 32 + j] * att_w[h * 3072 + (64 + j) * 32 + k];
        g_Apos[t] = s;
    } else if (t < 129 * 128 + 256) {
        int i = t - 129 * 128;
        int r = i / 4, h = i % 4;
        float s = 0.f;
        #pragma unroll
        for (int j = 0; j < 32; j++)
            s += E_deprel[r * 32 + j] * edge_w[h * 96 + j];
        g_Bdr[i] = s;
    } else if (t < 129 * 128 + 256 + 32) {
        int i = t - 129 * 128 - 256;
        int a = i / 4, h = i % 4;
        float s = 0.f;
        #pragma unroll
        for (int j = 0; j < 32; j++)
            s += E_deparc[a * 32 + j] * edge_w[h * 96 + 32 + j];
        g_Bda[i] = s;
    }
}

// ------------------- tf32 tensor-core GEMM -------------------
// C[M,N] = A[M,K] @ B[K,N], B given TRANSPOSED as BT[N,K] row-major.
// BM=128 BN=64 BK=32, 256 threads (8 warps), warp tile 32x32 via mma.m16n8k8 tf32.
__device__ __forceinline__ unsigned f2tf(float x) {
    unsigned r;
    asm("cvt.rna.tf32.f32 %0, %1;" : "=r"(r) : "f"(x));
    return r;
}

__device__ __forceinline__ void mma_tf32(float* c, const unsigned* a, const unsigned* b) {
    asm volatile(
        "mma.sync.aligned.m16n8k8.row.col.f32.tf32.tf32.f32 "
        "{%0,%1,%2,%3}, {%4,%5,%6,%7}, {%8,%9}, {%0,%1,%2,%3};"
        : "+f"(c[0]), "+f"(c[1]), "+f"(c[2]), "+f"(c[3])
        : "r"(a[0]), "r"(a[1]), "r"(a[2]), "r"(a[3]), "r"(b[0]), "r"(b[1]));
}

#define AS_STRIDE 36

__device__ __forceinline__ void gemm_tf32_body(int M, int K,
                                               const float* __restrict__ A, int lda,
                                               const float* __restrict__ BT, int ldbt,
                                               float* __restrict__ C, int ldc,
                                               const float* __restrict__ bias,
                                               unsigned* As /*128*36*/, unsigned* Bs /*64*36*/) {
    int m0 = blockIdx.y * 128;
    int n0 = blockIdx.x * 64;
    int tid = threadIdx.x;
    int wid = tid >> 5, lane = tid & 31;
    int wm = (wid & 3) * 32;   // warp row base in tile
    int wn = (wid >> 2) * 32;  // warp col base in tile
    int r = lane >> 2, cq = lane & 3;

    float acc[2][4][4];
    #pragma unroll
    for (int i = 0; i < 2; i++)
        #pragma unroll
        for (int j = 0; j < 4; j++)
            #pragma unroll
            for (int q = 0; q < 4; q++) acc[i][j][q] = 0.f;

    for (int k0 = 0; k0 < K; k0 += 32) {
        // stage A tile: 128x32 -> As[row][k], stride 36, tf32-converted
        #pragma unroll
        for (int l = 0; l < 4; l++) {
            int idx = tid + l * 256;            // 1024 float4
            int row = idx >> 3;
            int c4 = (idx & 7) * 4;
            float4 av = make_float4(0.f, 0.f, 0.f, 0.f);
            if (m0 + row < M)
                av = *(const float4*)(A + (size_t)(m0 + row) * lda + k0 + c4);
            unsigned* p = As + row * AS_STRIDE + c4;
            p[0] = f2tf(av.x); p[1] = f2tf(av.y); p[2] = f2tf(av.z); p[3] = f2tf(av.w);
        }
        // stage BT tile: 64x32 -> Bs[n][k]
        #pragma unroll
        for (int l = 0; l < 2; l++) {
            int idx = tid + l * 256;            // 512 float4
            int row = idx >> 3;
            int c4 = (idx & 7) * 4;
            float4 bv = *(const float4*)(BT + (size_t)(n0 + row) * ldbt + k0 + c4);
            unsigned* p = Bs + row * AS_STRIDE + c4;
            p[0] = f2tf(bv.x); p[1] = f2tf(bv.y); p[2] = f2tf(bv.z); p[3] = f2tf(bv.w);
        }
        __syncthreads();

        #pragma unroll
        for (int kf = 0; kf < 4; kf++) {
            int kb = kf * 8;
            unsigned afr[2][4], bfr[4][2];
            #pragma unroll
            for (int mf = 0; mf < 2; mf++) {
                const unsigned* base = As + (wm + mf * 16 + r) * AS_STRIDE + kb + cq;
                afr[mf][0] = base[0];
                afr[mf][1] = base[8 * AS_STRIDE];
                afr[mf][2] = base[4];
                afr[mf][3] = base[8 * AS_STRIDE + 4];
            }
            #pragma unroll
            for (int nf = 0; nf < 4; nf++) {
                const unsigned* base = Bs + (wn + nf * 8 + r) * AS_STRIDE + kb + cq;
                bfr[nf][0] = base[0];
                bfr[nf][1] = base[4];
            }
            #pragma unroll
            for (int mf = 0; mf < 2; mf++)
                #pragma unroll
                for (int nf = 0; nf < 4; nf++)
                    mma_tf32(acc[mf][nf], afr[mf], bfr[nf]);
        }
        __syncthreads();
    }

    // writeback: c0,c1 at (row, 2*cq..), c2,c3 at (row+8, ...)
    #pragma unroll
    for (int mf = 0; mf < 2; mf++) {
        #pragma unroll
        for (int nf = 0; nf < 4; nf++) {
            int col = n0 + wn + nf * 8 + cq * 2;
            float b0 = 0.f, b1 = 0.f;
            if (bias) { b0 = bias[col]; b1 = bias[col + 1]; }
            int row0 = m0 + wm + mf * 16 + r;
            if (row0 < M)
                *(float2*)(C + (size_t)row0 * ldc + col) =
                    make_float2(acc[mf][nf][0] + b0, acc[mf][nf][1] + b1);
            int row1 = row0 + 8;
            if (row1 < M)
                *(float2*)(C + (size_t)row1 * ldc + col) =
                    make_float2(acc[mf][nf][2] + b0, acc[mf][nf][3] + b1);
        }
    }
}

__global__ void gemm1_kernel(const float* __restrict__ inp) {
    __shared__ unsigned As[128 * AS_STRIDE];
    __shared__ unsigned Bs[64 * AS_STRIDE];
    gemm_tf32_body(NN, 256, inp, 256, g_WcatT, 256, g_big, 384, nullptr, As, Bs);
}

__global__ void gemm2_kernel(const float* __restrict__ bias,
                             float* __restrict__ out) {
    __shared__ unsigned As[128 * AS_STRIDE];
    __shared__ unsigned Bs[64 * AS_STRIDE];
    gemm_tf32_body(NN, 128, g_agg, 128, g_WfT, 128, out, 256, bias, As, Bs);
}

// ------------------- edge/attention kernel: one warp per target node -------------------
__device__ __forceinline__ float warpsum(float v) {
    #pragma unroll
    for (int o = 16; o > 0; o >>= 1) v += __shfl_xor_sync(0xffffffffu, v, o);
    return v;
}

__global__ void edge_kernel(const int* __restrict__ edge_index,
                            const int* __restrict__ relpos,
                            const int* __restrict__ deprel,
                            const int* __restrict__ deparc,
                            const float* __restrict__ edge_w,
                            float* __restrict__ attn) {
    int warp = (blockIdx.x * blockDim.x + threadIdx.x) >> 5;
    int lane = threadIdx.x & 31;
    if (warp >= NN) return;
    int n = warp;
    const int* src = edge_index;

    float at[4], ewn[4], den[4], acc[4];
    #pragma unroll
    for (int h = 0; h < 4; h++) {
        at[h]  = g_big[n * 384 + 256 + h * 32 + lane];
        ewn[h] = edge_w[h * 96 + 64 + lane];
        den[h] = 0.f;
        acc[h] = 0.f;
    }

    int d = g_cnt[n];
    if (d > MAXDEG) d = MAXDEG;
    const int* sl = g_slot + n * MAXDEG;

    // pass 1: denominators only (exp recomputed in pass 2 -> no 256MB spill buffer)
    for (int i = 0; i < d; i++) {
        int e = sl[i];
        int s = src[e];
        int p = relpos[e] + 64;
        const float* as = g_big + s * 384 + 128;
        const float* ap = g_Apos + p * 128;
        #pragma unroll
        for (int h = 0; h < 4; h++) {
            float x = as[h * 32 + lane] + at[h] + ap[h * 32 + lane];
            x = (x >= 0.f) ? x : 0.2f * x;          // leaky
            den[h] += __expf(x);
        }
    }

    // fold 1/(den+eps) into the beta->edge weights
    #pragma unroll
    for (int h = 0; h < 4; h++)
        ewn[h] = ewn[h] / (den[h] + 1e-12f);

    // pass 2: recompute exp, edge scores, attn output, weighted v accumulation
    for (int i = 0; i < d; i++) {
        int e = sl[i];
        int s = src[e];
        int p = relpos[e] + 64;
        const float* as = g_big + s * 384 + 128;
        const float* ap = g_Apos + p * 128;
        const float* vv = g_big + s * 384;
        int dr = deprel[e], da = deparc[e];
        float ex[4];
        #pragma unroll
        for (int h = 0; h < 4; h++) {
            float x = as[h * 32 + lane] + at[h] + ap[h * 32 + lane];
            x = (x >= 0.f) ? x : 0.2f * x;
            ex[h] = __expf(x);
        }
        float es[4];
        #pragma unroll
        for (int h = 0; h < 4; h++) {
            float b = warpsum(ex[h] * ewn[h]);
            float x = g_Bdr[dr * 4 + h] + g_Bda[da * 4 + h] + b;
            es[h] = (x >= 0.f) ? x : 0.2f * x;
            acc[h] += vv[h * 32 + lane] * es[h];
        }
        if (lane == 0)
            *(float4*)(attn + (size_t)e * 4) = make_float4(es[0], es[1], es[2], es[3]);
    }

    #pragma unroll
    for (int h = 0; h < 4; h++)
        g_agg[n * 128 + h * 32 + lane] = acc[h];
}

// ------------------- launch -------------------
extern "C" void kernel_launch(void* const* d_in, const int* in_sizes, int n_in,
                              void* d_out, int out_size) {
    const float* inp       = (const float*)d_in[0];
    const int*   relpos    = (const int*)d_in[1];
    // d_in[2] word_rel_pos_edge: unused
    // d_in[3] deprel_ext_edge: unused
    const int*   edge_index = (const int*)d_in[4];
    const int*   deprel    = (const int*)d_in[5];
    const int*   deparc    = (const int*)d_in[6];
    const float* Wkq       = (const float*)d_in[7];
    const float* Wv        = (const float*)d_in[8];
    const float* att_w     = (const float*)d_in[9];
    const float* edge_w    = (const float*)d_in[10];
    const float* Wf        = (const float*)d_in[11];
    const float* final_bias = (const float*)d_in[12];
    const float* E_deprel  = (const float*)d_in[13];
    const float* E_deparc  = (const float*)d_in[14];
    const float* E_pos     = (const float*)d_in[15];

    float* out  = (float*)d_out;             // [N, 256]
    float* attn = out + (size_t)NN * DD;     // [E, 4]

    zero_cnt_kernel<<<(NN + 255) / 256, 256>>>();
    prep_weights_kernel<<<(256 * 384 + 128 * 256 + 255) / 256, 256>>>(Wkq, Wv, att_w, Wf);
    prep_tables_kernel<<<(129 * 128 + 256 + 32 + 255) / 256, 256>>>(E_pos, E_deprel, E_deparc, att_w, edge_w);
    scatter_kernel<<<(EE + 255) / 256, 256>>>(edge_index);

    {
        dim3 grid(384 / 64, (NN + 127) / 128);
        gemm1_kernel<<<grid, 256>>>(inp);
    }

    edge_kernel<<<(NN * 32 + 255) / 256, 256>>>(edge_index, relpos, deprel, deparc, edge_w, attn);

    {
        dim3 grid(256 / 64, (NN + 127) / 128);
        gemm2_kernel<<<grid, 256>>>(final_bias, out);
    }
}

// round 3
// speedup vs baseline: 2.4856x; 1.1833x over previous
#include <cuda_runtime.h>
#include <cuda_bf16.h>

#define NN 50000
#define EE 500000
#define DD 256
#define HH 4
#define MAXDEG 96

// ------------------- device scratch (no allocations allowed) -------------------
// Column layouts are PERMUTED: within each 128-col section, col = lane*4 + h
// (lane = 0..31 is the ATT/DV index, h = head). This makes edge-kernel gathers float4.
__device__ float g_WcatT[384 * 256];    // [n=384][k=256], tf32-rounded. rows: 0-127 v | 128-255 A_src | 256-383 A_tgt
__device__ float g_WfT[256 * 128];      // [n=256][k=128], tf32-rounded, k permuted to match g_agg
__device__ float g_big[NN * 384];       // [N, 384] fp32, permuted sections
__device__ float g_Apos[129 * 128];     // [pos][lane*4+h] fp32
__device__ float g_Bdr[64 * 4];
__device__ float g_Bda[8 * 4];
__device__ float g_agg[NN * 128];       // [n][lane*4+h], tf32-rounded (GEMM2 A operand)
__device__ int   g_cnt[NN];
__device__ int   g_slot[NN * MAXDEG];

// ------------------- helpers -------------------
__device__ __forceinline__ unsigned f2tf(float x) {
    unsigned r;
    asm("cvt.rna.tf32.f32 %0, %1;" : "=r"(r) : "f"(x));
    return r;
}
__device__ __forceinline__ float f2tff(float x) { return __uint_as_float(f2tf(x)); }

__device__ __forceinline__ void cp_async16(void* smem, const void* gmem, bool pred) {
    unsigned sa = (unsigned)__cvta_generic_to_shared(smem);
    int sz = pred ? 16 : 0;
    asm volatile("cp.async.cg.shared.global [%0], [%1], 16, %2;" :: "r"(sa), "l"(gmem), "r"(sz));
}
__device__ __forceinline__ void cp_commit() { asm volatile("cp.async.commit_group;"); }
__device__ __forceinline__ void cp_wait0()  { asm volatile("cp.async.wait_group 0;" ::: "memory"); }

__device__ __forceinline__ void mma_tf32(float* c, const unsigned* a, const unsigned* b) {
    asm volatile(
        "mma.sync.aligned.m16n8k8.row.col.f32.tf32.tf32.f32 "
        "{%0,%1,%2,%3}, {%4,%5,%6,%7}, {%8,%9}, {%0,%1,%2,%3};"
        : "+f"(c[0]), "+f"(c[1]), "+f"(c[2]), "+f"(c[3])
        : "r"(a[0]), "r"(a[1]), "r"(a[2]), "r"(a[3]), "r"(b[0]), "r"(b[1]));
}

__device__ __forceinline__ float warpsum(float v) {
    #pragma unroll
    for (int o = 16; o > 0; o >>= 1) v += __shfl_xor_sync(0xffffffffu, v, o);
    return v;
}

// ------------------- small prep kernels -------------------
__global__ void zero_cnt_kernel() {
    int i = blockIdx.x * blockDim.x + threadIdx.x;
    if (i < NN) g_cnt[i] = 0;
}

__global__ void scatter_kernel(const int* __restrict__ edge_index) {
    int e = blockIdx.x * blockDim.x + threadIdx.x;
    if (e >= EE) return;
    int t = edge_index[EE + e];               // tgt
    int r = atomicAdd(&g_cnt[t], 1);
    if (r < MAXDEG) g_slot[t * MAXDEG + r] = e;
}

// WcatT (permuted columns, tf32-rounded) and WfT (permuted k, tf32-rounded)
__global__ void prep_weights_kernel(const float* __restrict__ Wkq,
                                    const float* __restrict__ Wv,
                                    const float* __restrict__ att_w,
                                    const float* __restrict__ Wf) {
    int t = blockIdx.x * blockDim.x + threadIdx.x;
    if (t < 384 * 256) {
        int c = t >> 8, d = t & 255;          // c = output row (n), d = k
        int sec = c >> 7;                     // 0: v, 1: A_src, 2: A_tgt
        int m = c & 127;
        int lane = m >> 2, h = m & 3;
        float o;
        if (sec == 0) {
            o = Wv[d * 128 + h * 32 + lane];
        } else {
            int joff = (sec == 2) ? 32 : 0;
            float s = 0.f;
            #pragma unroll
            for (int j = 0; j < 32; j++)
                s += Wkq[d * 128 + h * 32 + j] * att_w[h * 3072 + (joff + j) * 32 + lane];
            o = s;
        }
        g_WcatT[c * 256 + d] = f2tff(o);
    } else if (t < 384 * 256 + 256 * 128) {
        int i = t - 384 * 256;
        int c = i & 127, n = i >> 7;
        int k_orig = (c & 3) * 32 + (c >> 2);
        g_WfT[n * 128 + c] = f2tff(Wf[k_orig * 256 + n]);
    }
}

// A_pos table (permuted), Bdr, Bda
__global__ void prep_tables_kernel(const float* __restrict__ E_pos,
                                   const float* __restrict__ E_deprel,
                                   const float* __restrict__ E_deparc,
                                   const float* __restrict__ att_w,
                                   const float* __restrict__ edge_w) {
    int t = blockIdx.x * blockDim.x + threadIdx.x;
    if (t < 129 * 128) {
        int p = t >> 7, m = t & 127;
        int lane = m >> 2, h = m & 3;
        float s = 0.f;
        #pragma unroll
        for (int j = 0; j < 32; j++)
            s += E_pos[p * 32 + j] * att_w[h * 3072 + (64 + j) * 32 + lane];
        g_Apos[t] = s;
    } else if (t < 129 * 128 + 256) {
        int i = t - 129 * 128;
        int r = i / 4, h = i % 4;
        float s = 0.f;
        #pragma unroll
        for (int j = 0; j < 32; j++)
            s += E_deprel[r * 32 + j] * edge_w[h * 96 + j];
        g_Bdr[i] = s;
    } else if (t < 129 * 128 + 256 + 32) {
        int i = t - 129 * 128 - 256;
        int a = i / 4, h = i % 4;
        float s = 0.f;
        #pragma unroll
        for (int j = 0; j < 32; j++)
            s += E_deparc[a * 32 + j] * edge_w[h * 96 + 32 + j];
        g_Bda[i] = s;
    }
}

// ------------------- tf32 tensor-core GEMM, cp.async double-buffered -------------------
// C[M,N] = A[M,K] @ BT[N,K]^T. BM=128 BN=64 BK=32, 256 threads, warp tile 32x32.
// Smem uses XOR chunk swizzle (16B chunks) -> conflict-free fragment LDS, cp.async-aligned.
template<bool ACVT>
__device__ __forceinline__ void gemm_body(int M, int K,
                                          const float* __restrict__ A, int lda,
                                          const float* __restrict__ BT, int ldbt,
                                          float* __restrict__ C, int ldc,
                                          const float* __restrict__ bias,
                                          float (*As)[128 * 32], float (*Bs)[64 * 32]) {
    int m0 = blockIdx.y * 128;
    int n0 = blockIdx.x * 64;
    int tid = threadIdx.x;
    int wid = tid >> 5, lane = tid & 31;
    int wm = (wid & 3) * 32;
    int wn = (wid >> 2) * 32;
    int r = lane >> 2, cq = lane & 3;

    float acc[2][4][4];
    #pragma unroll
    for (int i = 0; i < 2; i++)
        #pragma unroll
        for (int j = 0; j < 4; j++)
            #pragma unroll
            for (int q = 0; q < 4; q++) acc[i][j][q] = 0.f;

    // staging lambda: tile k0 -> buffer buf
    auto stage = [&](int buf, int k0) {
        #pragma unroll
        for (int l = 0; l < 4; l++) {
            int idx = tid + l * 256;              // 1024 chunks of A
            int row = idx >> 3, c = idx & 7;
            float* dst = As[buf] + row * 32 + ((c ^ (row & 7)) << 2);
            const float* src = A + (size_t)(m0 + row) * lda + k0 + c * 4;
            cp_async16(dst, src, m0 + row < M);
        }
        #pragma unroll
        for (int l = 0; l < 2; l++) {
            int idx = tid + l * 256;              // 512 chunks of B
            int row = idx >> 3, c = idx & 7;
            float* dst = Bs[buf] + row * 32 + ((c ^ (row & 7)) << 2);
            const float* src = BT + (size_t)(n0 + row) * ldbt + k0 + c * 4;
            cp_async16(dst, src, true);
        }
    };

    int T = K >> 5;
    stage(0, 0);
    cp_commit();

    for (int t = 0; t < T; t++) {
        cp_wait0();
        __syncthreads();
        if (t + 1 < T) { stage((t + 1) & 1, (t + 1) * 32); cp_commit(); }

        const float* Ab = As[t & 1];
        const float* Bb = Bs[t & 1];
        #pragma unroll
        for (int kf = 0; kf < 4; kf++) {
            int ch0 = 2 * kf, ch1 = 2 * kf + 1;
            int o0 = ((ch0 ^ r) << 2) + cq;
            int o1 = ((ch1 ^ r) << 2) + cq;
            unsigned afr[2][4], bfr[4][2];
            #pragma unroll
            for (int mf = 0; mf < 2; mf++) {
                const float* b0 = Ab + (wm + mf * 16 + r) * 32;
                const float* b8 = b0 + 8 * 32;
                if (ACVT) {
                    afr[mf][0] = f2tf(b0[o0]); afr[mf][1] = f2tf(b8[o0]);
                    afr[mf][2] = f2tf(b0[o1]); afr[mf][3] = f2tf(b8[o1]);
                } else {
                    afr[mf][0] = __float_as_uint(b0[o0]); afr[mf][1] = __float_as_uint(b8[o0]);
                    afr[mf][2] = __float_as_uint(b0[o1]); afr[mf][3] = __float_as_uint(b8[o1]);
                }
            }
            #pragma unroll
            for (int nf = 0; nf < 4; nf++) {
                const float* bb = Bb + (wn + nf * 8 + r) * 32;
                bfr[nf][0] = __float_as_uint(bb[o0]);
                bfr[nf][1] = __float_as_uint(bb[o1]);
            }
            #pragma unroll
            for (int mf = 0; mf < 2; mf++)
                #pragma unroll
                for (int nf = 0; nf < 4; nf++)
                    mma_tf32(acc[mf][nf], afr[mf], bfr[nf]);
        }
        __syncthreads();
    }

    #pragma unroll
    for (int mf = 0; mf < 2; mf++) {
        #pragma unroll
        for (int nf = 0; nf < 4; nf++) {
            int col = n0 + wn + nf * 8 + cq * 2;
            float b0 = 0.f, b1 = 0.f;
            if (bias) { b0 = bias[col]; b1 = bias[col + 1]; }
            int row0 = m0 + wm + mf * 16 + r;
            if (row0 < M)
                *(float2*)(C + (size_t)row0 * ldc + col) =
                    make_float2(acc[mf][nf][0] + b0, acc[mf][nf][1] + b1);
            int row1 = row0 + 8;
            if (row1 < M)
                *(float2*)(C + (size_t)row1 * ldc + col) =
                    make_float2(acc[mf][nf][2] + b0, acc[mf][nf][3] + b1);
        }
    }
}

__global__ void gemm1_kernel(const float* __restrict__ inp) {
    __shared__ float As[2][128 * 32];
    __shared__ float Bs[2][64 * 32];
    gemm_body<true>(NN, 256, inp, 256, g_WcatT, 256, g_big, 384, nullptr, As, Bs);
}

__global__ void gemm2_kernel(const float* __restrict__ bias,
                             float* __restrict__ out) {
    __shared__ float As[2][128 * 32];
    __shared__ float Bs[2][64 * 32];
    gemm_body<false>(NN, 128, g_agg, 128, g_WfT, 128, out, 256, bias, As, Bs);
}

// ------------------- edge/attention kernel: one warp per target node -------------------
__global__ void edge_kernel(const int* __restrict__ edge_index,
                            const int* __restrict__ relpos,
                            const int* __restrict__ deprel,
                            const int* __restrict__ deparc,
                            const float* __restrict__ edge_w,
                            float* __restrict__ attn) {
    int warp = (blockIdx.x * blockDim.x + threadIdx.x) >> 5;
    int lane = threadIdx.x & 31;
    if (warp >= NN) return;
    int n = warp;
    const int* src = edge_index;

    float4 at4 = *(const float4*)(g_big + (size_t)n * 384 + 256 + lane * 4);
    float ewn[4], den[4], acc[4];
    #pragma unroll
    for (int h = 0; h < 4; h++) {
        ewn[h] = edge_w[h * 96 + 64 + lane];
        den[h] = 0.f;
        acc[h] = 0.f;
    }

    int d = g_cnt[n];
    if (d > MAXDEG) d = MAXDEG;
    const int* sl = g_slot + n * MAXDEG;
    // cooperative slot load into registers
    int se0 = sl[lane], se1 = sl[lane + 32], se2 = sl[lane + 64];
    auto get_e = [&](int i) {
        int v = (i < 32) ? se0 : ((i < 64) ? se1 : se2);
        return __shfl_sync(0xffffffffu, v, i & 31);
    };

    // pass 1: denominators (exp recomputed in pass 2; no spill buffer)
    {
        int e = 0, s = 0, p = 0;
        if (d > 0) { e = get_e(0); s = src[e]; p = relpos[e] + 64; }
        for (int i = 0; i < d; i++) {
            int en = e, sn = s, pn = p;
            if (i + 1 < d) { en = get_e(i + 1); sn = src[en]; pn = relpos[en] + 64; }
            float4 as4 = *(const float4*)(g_big + (size_t)s * 384 + 128 + lane * 4);
            float4 ap4 = *(const float4*)(g_Apos + p * 128 + lane * 4);
            float x0 = as4.x + at4.x + ap4.x; x0 = (x0 >= 0.f) ? x0 : 0.2f * x0;
            float x1 = as4.y + at4.y + ap4.y; x1 = (x1 >= 0.f) ? x1 : 0.2f * x1;
            float x2 = as4.z + at4.z + ap4.z; x2 = (x2 >= 0.f) ? x2 : 0.2f * x2;
            float x3 = as4.w + at4.w + ap4.w; x3 = (x3 >= 0.f) ? x3 : 0.2f * x3;
            den[0] += __expf(x0); den[1] += __expf(x1);
            den[2] += __expf(x2); den[3] += __expf(x3);
            e = en; s = sn; p = pn;
        }
    }

    // fold 1/(den+eps) into beta weights (per-lane, per-head)
    #pragma unroll
    for (int h = 0; h < 4; h++)
        ewn[h] = ewn[h] / (den[h] + 1e-12f);

    // pass 2: recompute exp, edge scores, attn, weighted v accumulation
    {
        int e = 0, s = 0, p = 0, dr = 0, da = 0;
        if (d > 0) { e = get_e(0); s = src[e]; p = relpos[e] + 64; dr = deprel[e]; da = deparc[e]; }
        for (int i = 0; i < d; i++) {
            int en = e, sn = s, pn = p, drn = dr, dan = da;
            if (i + 1 < d) {
                en = get_e(i + 1); sn = src[en]; pn = relpos[en] + 64;
                drn = deprel[en]; dan = deparc[en];
            }
            float4 as4 = *(const float4*)(g_big + (size_t)s * 384 + 128 + lane * 4);
            float4 ap4 = *(const float4*)(g_Apos + p * 128 + lane * 4);
            float4 vv4 = *(const float4*)(g_big + (size_t)s * 384 + lane * 4);
            float x0 = as4.x + at4.x + ap4.x; x0 = (x0 >= 0.f) ? x0 : 0.2f * x0;
            float x1 = as4.y + at4.y + ap4.y; x1 = (x1 >= 0.f) ? x1 : 0.2f * x1;
            float x2 = as4.z + at4.z + ap4.z; x2 = (x2 >= 0.f) ? x2 : 0.2f * x2;
            float x3 = as4.w + at4.w + ap4.w; x3 = (x3 >= 0.f) ? x3 : 0.2f * x3;
            float b0 = warpsum(__expf(x0) * ewn[0]);
            float b1 = warpsum(__expf(x1) * ewn[1]);
            float b2 = warpsum(__expf(x2) * ewn[2]);
            float b3 = warpsum(__expf(x3) * ewn[3]);
            float y0 = g_Bdr[dr * 4 + 0] + g_Bda[da * 4 + 0] + b0;
            float y1 = g_Bdr[dr * 4 + 1] + g_Bda[da * 4 + 1] + b1;
            float y2 = g_Bdr[dr * 4 + 2] + g_Bda[da * 4 + 2] + b2;
            float y3 = g_Bdr[dr * 4 + 3] + g_Bda[da * 4 + 3] + b3;
            float es0 = (y0 >= 0.f) ? y0 : 0.2f * y0;
            float es1 = (y1 >= 0.f) ? y1 : 0.2f * y1;
            float es2 = (y2 >= 0.f) ? y2 : 0.2f * y2;
            float es3 = (y3 >= 0.f) ? y3 : 0.2f * y3;
            acc[0] += vv4.x * es0;
            acc[1] += vv4.y * es1;
            acc[2] += vv4.z * es2;
            acc[3] += vv4.w * es3;
            if (lane == 0)
                *(float4*)(attn + (size_t)e * 4) = make_float4(es0, es1, es2, es3);
            e = en; s = sn; p = pn; dr = drn; da = dan;
        }
    }

    // write agg (tf32-rounded so GEMM2 skips conversion)
    float4 o = make_float4(f2tff(acc[0]), f2tff(acc[1]), f2tff(acc[2]), f2tff(acc[3]));
    *(float4*)(g_agg + (size_t)n * 128 + lane * 4) = o;
}

// ------------------- launch -------------------
extern "C" void kernel_launch(void* const* d_in, const int* in_sizes, int n_in,
                              void* d_out, int out_size) {
    const float* inp       = (const float*)d_in[0];
    const int*   relpos    = (const int*)d_in[1];
    // d_in[2] word_rel_pos_edge: unused
    // d_in[3] deprel_ext_edge: unused
    const int*   edge_index = (const int*)d_in[4];
    const int*   deprel    = (const int*)d_in[5];
    const int*   deparc    = (const int*)d_in[6];
    const float* Wkq       = (const float*)d_in[7];
    const float* Wv        = (const float*)d_in[8];
    const float* att_w     = (const float*)d_in[9];
    const float* edge_w    = (const float*)d_in[10];
    const float* Wf        = (const float*)d_in[11];
    const float* final_bias = (const float*)d_in[12];
    const float* E_deprel  = (const float*)d_in[13];
    const float* E_deparc  = (const float*)d_in[14];
    const float* E_pos     = (const float*)d_in[15];

    float* out  = (float*)d_out;             // [N, 256]
    float* attn = out + (size_t)NN * DD;     // [E, 4]

    zero_cnt_kernel<<<(NN + 255) / 256, 256>>>();
    prep_weights_kernel<<<(384 * 256 + 256 * 128 + 255) / 256, 256>>>(Wkq, Wv, att_w, Wf);
    prep_tables_kernel<<<(129 * 128 + 256 + 32 + 255) / 256, 256>>>(E_pos, E_deprel, E_deparc, att_w, edge_w);
    scatter_kernel<<<(EE + 255) / 256, 256>>>(edge_index);

    {
        dim3 grid(384 / 64, (NN + 127) / 128);
        gemm1_kernel<<<grid, 256>>>(inp);
    }

    edge_kernel<<<(NN * 32 + 255) / 256, 256>>>(edge_index, relpos, deprel, deparc, edge_w, attn);

    {
        dim3 grid(256 / 64, (NN + 127) / 128);
        gemm2_kernel<<<grid, 256>>>(final_bias, out);
    }
}